// round 6
// baseline (speedup 1.0000x reference)
#include <cuda_runtime.h>
#include <cuda_fp16.h>
#include <cstdint>

#define NPTS 8192
#define KN   32
#define DIM  256
#define DIMH 128
#define DOUT 512
#define LDT  36

// ---------------- device scratch (allocation-free rule) ----------------
__device__ float  g_qattn[NPTS * DIM];
__device__ float  g_respre[NPTS * DIM];
__device__ __half g_vpe[(size_t)NPTS * KN * DIM];   // v + pos_encode, fp16
__device__ __half g_WkTn[DIM * DIM];    // -Wk^T  [n][k]
__device__ __half g_WvT [DIM * DIM];    // Wv^T
__device__ __half g_g1T [DIM * DIM];
__device__ __half g_g2T [DIM * DIM];
__device__ __half g_d2T [DIM * DIMH];   // d2^T [n=256][k=128]

// ---------------- merged weight transpose/convert ----------------
extern "C" __global__ void convert_all(const float* __restrict__ Wk,
                                       const float* __restrict__ Wv,
                                       const float* __restrict__ g1w,
                                       const float* __restrict__ g2w,
                                       const float* __restrict__ d2w) {
    int idx = blockIdx.x * 256 + threadIdx.x;
    if (idx < 65536) {
        int n = idx >> 8, k = idx & 255;
        g_WkTn[idx] = __float2half(-Wk[k * 256 + n]);
    } else if (idx < 131072) {
        int i = idx - 65536; int n = i >> 8, k = i & 255;
        g_WvT[i] = __float2half(Wv[k * 256 + n]);
    } else if (idx < 196608) {
        int i = idx - 131072; int n = i >> 8, k = i & 255;
        g_g1T[i] = __float2half(g1w[k * 256 + n]);
    } else if (idx < 262144) {
        int i = idx - 196608; int n = i >> 8, k = i & 255;
        g_g2T[i] = __float2half(g2w[k * 256 + n]);
    } else if (idx < 294912) {
        int i = idx - 262144; int n = i >> 7, k = i & 127;
        g_d2T[i] = __float2half(d2w[k * 256 + n]);
    }
}

extern "C" __global__ void copy_xyz_kernel(const float* __restrict__ src,
                                           float* __restrict__ dst, int n) {
    int i = blockIdx.x * blockDim.x + threadIdx.x;
    if (i < n) dst[i] = src[i];
}

// ---------------- fp32 column-GEMM (q / out projections) -------
union F2U { float2 f; unsigned long long u; };
__device__ __forceinline__ void ffma2(float2& d, const float2 a, const float2 b) {
    F2U du, au, bu; du.f = d; au.f = a; bu.f = b;
    asm("fma.rn.f32x2 %0, %1, %2, %0;" : "+l"(du.u) : "l"(au.u), "l"(bu.u));
    d = du.f;
}
template <int KK, int NC>
__device__ __forceinline__ void colgemm(const float* __restrict__ At,
                                        const float* __restrict__ W,
                                        int c, float2 (&acc)[16]) {
#pragma unroll 4
    for (int kk = 0; kk < KK; ++kk) {
        float w = __ldg(W + kk * NC + c);
        float2 w2 = make_float2(w, w);
        const float4* a4 = reinterpret_cast<const float4*>(At + kk * LDT);
#pragma unroll
        for (int i = 0; i < 8; ++i) {
            float4 a = a4[i];
            ffma2(acc[2 * i],     make_float2(a.x, a.y), w2);
            ffma2(acc[2 * i + 1], make_float2(a.z, a.w), w2);
        }
    }
}

extern "C" __global__ void __launch_bounds__(256)
qproj_kernel(const float* __restrict__ feats_q, const float* __restrict__ Wq) {
    __shared__ float At[DIM * LDT];
    const int n0 = blockIdx.x * 32;
    const int f = threadIdx.x;
#pragma unroll
    for (int r = 0; r < 32; ++r) {
        At[f * LDT + r] = feats_q[(size_t)(n0 + r) * DIM + f];
    }
    __syncthreads();
    float2 acc[16];
#pragma unroll
    for (int i = 0; i < 16; ++i) { acc[i] = make_float2(0.f, 0.f); }
    colgemm<DIM, DIM>(At, Wq, f, acc);
#pragma unroll
    for (int i = 0; i < 16; ++i) {
        g_qattn[(size_t)(n0 + 2 * i) * DIM + f]     = acc[i].x;
        g_qattn[(size_t)(n0 + 2 * i + 1) * DIM + f] = acc[i].y;
    }
}

extern "C" __global__ void __launch_bounds__(256)
outproj_kernel(const float* __restrict__ ow, const float* __restrict__ ob,
               float* __restrict__ out, long long ofs) {
    __shared__ float At[DIM * LDT];
    const int n0 = (blockIdx.x >> 1) * 32;
    const int half = blockIdx.x & 1;
    const int t = threadIdx.x;
#pragma unroll
    for (int r = 0; r < 32; ++r) {
        At[t * LDT + r] = g_respre[(size_t)(n0 + r) * DIM + t];
    }
    __syncthreads();
    const int c = half * 256 + t;
    float2 acc[16];
    float b = ob[c];
#pragma unroll
    for (int i = 0; i < 16; ++i) { acc[i] = make_float2(b, b); }
    colgemm<DIM, DOUT>(At, ow, c, acc);
    float* dst = out + ofs;
#pragma unroll
    for (int i = 0; i < 16; ++i) {
        dst[(size_t)(n0 + 2 * i) * DOUT + c]     = acc[i].x;
        dst[(size_t)(n0 + 2 * i + 1) * DOUT + c] = acc[i].y;
    }
}

// =======================================================================
// Fused mma.sync kernel. CTA = 2 points = 64 rows x 256 feats,
// 256 threads = 8 warps, warp w owns cols [32w, 32w+32) (m64 x n32).
// Weight slabs: [256n x 32k] = 16KB, double-buffered cp.async.
// smem/CTA = 112KB -> 2 CTAs per SM (cross-CTA latency hiding).
// =======================================================================

#define F_OFF   0u        // 64 x 512B fp16 swizzled (feats; later A1)
#define H_OFF   32768u    // h tile
#define H1_OFF  65536u    // 64 x 256B fp16 swizzled
#define WS0_OFF 81920u    // weight slab buf 0 (16KB)
#define WS1_OFF 98304u    // weight slab buf 1 (16KB)
#define SMEM_FUSED 114688

__device__ __forceinline__ unsigned int swz(unsigned int row, unsigned int cb,
                                            unsigned int rb) {
    return row * rb + (cb ^ ((row & 7u) << 4));
}
__device__ __forceinline__ void cp_async16(unsigned int dst, const void* src) {
    asm volatile("cp.async.cg.shared.global [%0], [%1], 16;\n" :: "r"(dst), "l"(src) : "memory");
}
#define CP_COMMIT() asm volatile("cp.async.commit_group;\n" ::: "memory")
#define CP_WAIT(n)  asm volatile("cp.async.wait_group %0;\n" :: "n"(n) : "memory")

// stage one [256n x 32k] slab (16KB), tile-blocked:
// dst = ks*8192 + (n>>3)*256 + khalf*128 + (n&7)*16
__device__ __forceinline__ void stage_slab(unsigned int dstbase, int tid,
                                           const __half* __restrict__ Wsrc,
                                           int rowb, int colb) {
#pragma unroll
    for (int it = 0; it < 4; ++it) {
        int f = tid + it * 256;
        int ks = f >> 9, rem = f & 511;
        int t8 = rem >> 4, sub = rem & 15;
        int kh = sub >> 3, r = sub & 7;
        unsigned int dst = dstbase + (unsigned int)(ks * 8192 + t8 * 256 + kh * 128 + r * 16);
        const char* src = (const char*)Wsrc + (size_t)(t8 * 8 + r) * rowb + colb + ks * 32 + kh * 16;
        cp_async16(dst, src);
    }
}

// 2 ksteps of acc += A @ W^T for this warp's m64 x n32 tile
__device__ __forceinline__ void slab_compute(float (&acc)[4][4][4],
                                             unsigned int Abase, unsigned int arb,
                                             int aks0, unsigned int Wbase,
                                             int lane, int wn) {
    const int lr  = (lane & 7) + ((lane >> 3) & 1) * 8;
    const int lcb = ((lane >> 4) & 1) * 16;
    const int ntp = (lane >> 4) & 1;
    const int kh  = (lane >> 3) & 1;
    const int rr  = lane & 7;
#pragma unroll
    for (int ks = 0; ks < 2; ++ks) {
        unsigned int bf[2][4];
#pragma unroll
        for (int bg = 0; bg < 2; ++bg) {
            unsigned int ba = Wbase + (unsigned int)(ks * 8192)
                            + (unsigned int)(wn * 4 + bg * 2 + ntp) * 256u
                            + (unsigned int)(kh * 128 + rr * 16);
            asm volatile("ldmatrix.sync.aligned.m8n8.x4.shared.b16 {%0,%1,%2,%3}, [%4];\n"
                         : "=r"(bf[bg][0]), "=r"(bf[bg][1]), "=r"(bf[bg][2]), "=r"(bf[bg][3])
                         : "r"(ba));
        }
#pragma unroll
        for (int mt = 0; mt < 4; ++mt) {
            unsigned int a0, a1, a2, a3;
            unsigned int ad = Abase + swz((unsigned int)(mt * 16 + lr),
                                          (unsigned int)((aks0 + ks) * 32 + lcb), arb);
            asm volatile("ldmatrix.sync.aligned.m8n8.x4.shared.b16 {%0,%1,%2,%3}, [%4];\n"
                         : "=r"(a0), "=r"(a1), "=r"(a2), "=r"(a3) : "r"(ad));
#pragma unroll
            for (int nt = 0; nt < 4; ++nt) {
                asm volatile(
                    "mma.sync.aligned.m16n8k16.row.col.f32.f16.f16.f32 "
                    "{%0,%1,%2,%3},{%4,%5,%6,%7},{%8,%9},{%0,%1,%2,%3};\n"
                    : "+f"(acc[mt][nt][0]), "+f"(acc[mt][nt][1]),
                      "+f"(acc[mt][nt][2]), "+f"(acc[mt][nt][3])
                    : "r"(a0), "r"(a1), "r"(a2), "r"(a3),
                      "r"(bf[nt >> 1][(nt & 1) * 2]), "r"(bf[nt >> 1][(nt & 1) * 2 + 1]));
            }
        }
    }
}

// pipelined pass: n0s slabs from W0src (rowb 512) then n1s from W1src (rowb 256, d2)
__device__ __forceinline__ void run_pass(float (&acc)[4][4][4], unsigned int smb,
                                         int tid, int lane, int wn,
                                         const __half* W0src, int n0s,
                                         const __half* W1src, int n1s,
                                         unsigned int Aoff0, unsigned int arb0,
                                         unsigned int Aoff1, unsigned int arb1) {
    const int total = n0s + n1s;
    stage_slab(smb + WS0_OFF, tid, W0src, 512, 0);
    CP_COMMIT();
    for (int s = 0; s < total; ++s) {
        if (s + 1 < total) {
            int t = s + 1;
            const __half* Wsrc; int rowb, colb;
            if (t < n0s) { Wsrc = W0src; rowb = 512; colb = t * 64; }
            else         { Wsrc = W1src; rowb = 256; colb = (t - n0s) * 64; }
            stage_slab(smb + ((t & 1) ? WS1_OFF : WS0_OFF), tid, Wsrc, rowb, colb);
            CP_COMMIT();
            CP_WAIT(1);
        } else {
            CP_WAIT(0);
        }
        __syncthreads();
        unsigned int Ab, arb; int aks0;
        if (s < n0s) { Ab = smb + Aoff0; arb = arb0; aks0 = s * 2; }
        else         { Ab = smb + Aoff1; arb = arb1; aks0 = (s - n0s) * 2; }
        slab_compute(acc, Ab, arb, aks0, smb + ((s & 1) ? WS1_OFF : WS0_OFF), lane, wn);
        __syncthreads();
    }
}

extern "C" __global__ void __launch_bounds__(256, 2)
fused_mma(const float* __restrict__ xyz_q, const float* __restrict__ xyz_kv,
          const float* __restrict__ feats_kv,
          const float* __restrict__ d1w, const float* __restrict__ d1b,
          const float* __restrict__ d2b,
          const float* __restrict__ g1b, const float* __restrict__ g2b) {
    extern __shared__ char smem[];
    const unsigned int smb = (unsigned int)__cvta_generic_to_shared(smem);
    const int tid  = threadIdx.x;
    const int lane = tid & 31;
    const int wn   = tid >> 5;     // warp = n-region: cols [wn*32, wn*32+32)
    const int g    = lane >> 2, tig = lane & 3;
    const int p0   = blockIdx.x * 2;

    // ---- stage F: 64 x 256 fp32 -> fp16 swizzled (512B rows) ----
    {
        const float4* src = (const float4*)(feats_kv + (size_t)p0 * KN * DIM);
#pragma unroll
        for (int it = 0; it < 16; ++it) {
            int i = tid + it * 256;
            unsigned int row = (unsigned int)(i >> 6), c4 = (unsigned int)(i & 63);
            float4 v = __ldg(src + (size_t)row * 64 + c4);
            __half2 h01 = __floats2half2_rn(v.x, v.y);
            __half2 h23 = __floats2half2_rn(v.z, v.w);
            uint2 u = make_uint2(*(unsigned int*)&h01, *(unsigned int*)&h23);
            *(uint2*)(smem + F_OFF + swz(row, c4 * 8u, 512u)) = u;
        }
    }
    // ---- H1 = relu(rel @ d1 + b): 64 x 256B rows swizzled ----
    {
        unsigned int row = (unsigned int)(tid >> 2);
        int c0 = (tid & 3) * 32;
        int p = (int)(row >> 5), k = (int)(row & 31);
        float qx = __ldg(xyz_q + (p0 + p) * 3 + 0);
        float qy = __ldg(xyz_q + (p0 + p) * 3 + 1);
        float qz = __ldg(xyz_q + (p0 + p) * 3 + 2);
        const float* pk = xyz_kv + ((size_t)(p0 + p) * KN + k) * 3;
        float rx = qx - __ldg(pk + 0), ry = qy - __ldg(pk + 1), rz = qz - __ldg(pk + 2);
#pragma unroll 4
        for (int c = c0; c < c0 + 32; c += 2) {
            float h0 = fmaf(rx, __ldg(d1w + c),     fmaf(ry, __ldg(d1w + 128 + c),     fmaf(rz, __ldg(d1w + 256 + c),     __ldg(d1b + c))));
            float h1 = fmaf(rx, __ldg(d1w + c + 1), fmaf(ry, __ldg(d1w + 128 + c + 1), fmaf(rz, __ldg(d1w + 256 + c + 1), __ldg(d1b + c + 1))));
            __half2 hh = __floats2half2_rn(fmaxf(h0, 0.f), fmaxf(h1, 0.f));
            *(__half2*)(smem + H1_OFF + swz(row, (unsigned int)c * 2u, 256u)) = hh;
        }
    }
    __syncthreads();

    float acc[4][4][4];

    // =================== pass A: h = q - k + pe =========================
#pragma unroll
    for (int mt = 0; mt < 4; ++mt) {
#pragma unroll
        for (int nt = 0; nt < 4; ++nt) {
#pragma unroll
            for (int i = 0; i < 4; ++i) { acc[mt][nt][i] = 0.f; }
        }
    }
    run_pass(acc, smb, tid, lane, wn, g_WkTn, 8, g_d2T, 4, F_OFF, 512u, H1_OFF, 256u);
    // epilogue A: h -> Hbuf (+ q + d2b)
    {
        float2 qv0[4], qv1[4], db[4];
#pragma unroll
        for (int nt = 0; nt < 4; ++nt) {
            int c = wn * 32 + nt * 8 + 2 * tig;
            db[nt]  = make_float2(__ldg(d2b + c), __ldg(d2b + c + 1));
            qv0[nt] = make_float2(__ldg(g_qattn + (size_t)p0 * DIM + c),
                                  __ldg(g_qattn + (size_t)p0 * DIM + c + 1));
            qv1[nt] = make_float2(__ldg(g_qattn + (size_t)(p0 + 1) * DIM + c),
                                  __ldg(g_qattn + (size_t)(p0 + 1) * DIM + c + 1));
        }
#pragma unroll
        for (int mt = 0; mt < 4; ++mt) {
#pragma unroll
            for (int nt = 0; nt < 4; ++nt) {
                int c = wn * 32 + nt * 8 + 2 * tig;
                float2 q = (mt >> 1) ? qv1[nt] : qv0[nt];
                unsigned int row = (unsigned int)(mt * 16 + g);
                __half2 lo = __floats2half2_rn(acc[mt][nt][0] + q.x + db[nt].x,
                                               acc[mt][nt][1] + q.y + db[nt].y);
                __half2 hi = __floats2half2_rn(acc[mt][nt][2] + q.x + db[nt].x,
                                               acc[mt][nt][3] + q.y + db[nt].y);
                *(__half2*)(smem + H_OFF + swz(row,      (unsigned int)c * 2u, 512u)) = lo;
                *(__half2*)(smem + H_OFF + swz(row + 8u, (unsigned int)c * 2u, 512u)) = hi;
            }
        }
    }
    __syncthreads();

    // =================== pass B: vpe = v + pe -> global fp16 ============
#pragma unroll
    for (int mt = 0; mt < 4; ++mt) {
#pragma unroll
        for (int nt = 0; nt < 4; ++nt) {
#pragma unroll
            for (int i = 0; i < 4; ++i) { acc[mt][nt][i] = 0.f; }
        }
    }
    run_pass(acc, smb, tid, lane, wn, g_WvT, 8, g_d2T, 4, F_OFF, 512u, H1_OFF, 256u);
    {
#pragma unroll
        for (int nt = 0; nt < 4; ++nt) {
            int c = wn * 32 + nt * 8 + 2 * tig;
            float b0 = __ldg(d2b + c), b1 = __ldg(d2b + c + 1);
#pragma unroll
            for (int mt = 0; mt < 4; ++mt) {
                size_t grow = (size_t)blockIdx.x * 64 + (size_t)(mt * 16 + g);
                __half2 lo = __floats2half2_rn(acc[mt][nt][0] + b0, acc[mt][nt][1] + b1);
                __half2 hi = __floats2half2_rn(acc[mt][nt][2] + b0, acc[mt][nt][3] + b1);
                *(__half2*)(g_vpe + grow * DIM + c)       = lo;
                *(__half2*)(g_vpe + (grow + 8) * DIM + c) = hi;
            }
        }
    }
    __syncthreads();

    // =================== pass C: A1 = relu(h @ g1 + b) -> Fbuf ==========
#pragma unroll
    for (int mt = 0; mt < 4; ++mt) {
#pragma unroll
        for (int nt = 0; nt < 4; ++nt) {
#pragma unroll
            for (int i = 0; i < 4; ++i) { acc[mt][nt][i] = 0.f; }
        }
    }
    run_pass(acc, smb, tid, lane, wn, g_g1T, 8, (const __half*)0, 0, H_OFF, 512u, 0u, 0u);
    {
#pragma unroll
        for (int nt = 0; nt < 4; ++nt) {
            int c = wn * 32 + nt * 8 + 2 * tig;
            float b0 = __ldg(g1b + c), b1 = __ldg(g1b + c + 1);
#pragma unroll
            for (int mt = 0; mt < 4; ++mt) {
                unsigned int row = (unsigned int)(mt * 16 + g);
                __half2 lo = __floats2half2_rn(fmaxf(acc[mt][nt][0] + b0, 0.f),
                                               fmaxf(acc[mt][nt][1] + b1, 0.f));
                __half2 hi = __floats2half2_rn(fmaxf(acc[mt][nt][2] + b0, 0.f),
                                               fmaxf(acc[mt][nt][3] + b1, 0.f));
                *(__half2*)(smem + F_OFF + swz(row,      (unsigned int)c * 2u, 512u)) = lo;
                *(__half2*)(smem + F_OFF + swz(row + 8u, (unsigned int)c * 2u, 512u)) = hi;
            }
        }
    }
    __syncthreads();

    // =================== pass D: logits = A1 @ g2 + b; softmax ==========
#pragma unroll
    for (int mt = 0; mt < 4; ++mt) {
#pragma unroll
        for (int nt = 0; nt < 4; ++nt) {
#pragma unroll
            for (int i = 0; i < 4; ++i) { acc[mt][nt][i] = 0.f; }
        }
    }
    run_pass(acc, smb, tid, lane, wn, g_g2T, 8, (const __half*)0, 0, F_OFF, 512u, 0u, 0u);
    {
#pragma unroll
        for (int nt = 0; nt < 4; ++nt) {
            int c = wn * 32 + nt * 8 + 2 * tig;
            float gb0 = __ldg(g2b + c), gb1 = __ldg(g2b + c + 1);
            float2 vl[4], vh[4];
#pragma unroll
            for (int mt = 0; mt < 4; ++mt) {
                size_t grow = (size_t)blockIdx.x * 64 + (size_t)(mt * 16 + g);
                __half2 a = *(const __half2*)(g_vpe + grow * DIM + c);
                __half2 b = *(const __half2*)(g_vpe + (grow + 8) * DIM + c);
                vl[mt] = __half22float2(a);
                vh[mt] = __half22float2(b);
            }
#pragma unroll
            for (int ptl = 0; ptl < 2; ++ptl) {
                int mtb = 2 * ptl;
#pragma unroll
                for (int ci = 0; ci < 2; ++ci) {
                    float gb = ci ? gb1 : gb0;
                    float l0 = acc[mtb][nt][ci]         + gb;
                    float l1 = acc[mtb][nt][ci + 2]     + gb;
                    float l2 = acc[mtb + 1][nt][ci]     + gb;
                    float l3 = acc[mtb + 1][nt][ci + 2] + gb;
                    float v0 = ci ? vl[mtb].y     : vl[mtb].x;
                    float v1 = ci ? vh[mtb].y     : vh[mtb].x;
                    float v2 = ci ? vl[mtb + 1].y : vl[mtb + 1].x;
                    float v3 = ci ? vh[mtb + 1].y : vh[mtb + 1].x;
                    float mx = fmaxf(fmaxf(l0, l1), fmaxf(l2, l3));
                    mx = fmaxf(mx, __shfl_xor_sync(0xffffffffu, mx, 4));
                    mx = fmaxf(mx, __shfl_xor_sync(0xffffffffu, mx, 8));
                    mx = fmaxf(mx, __shfl_xor_sync(0xffffffffu, mx, 16));
                    float e0 = __expf(l0 - mx), e1 = __expf(l1 - mx);
                    float e2 = __expf(l2 - mx), e3 = __expf(l3 - mx);
                    float ss = (e0 + e1) + (e2 + e3);
                    float ws = (e0 * v0 + e1 * v1) + (e2 * v2 + e3 * v3);
                    ss += __shfl_xor_sync(0xffffffffu, ss, 4);
                    ws += __shfl_xor_sync(0xffffffffu, ws, 4);
                    ss += __shfl_xor_sync(0xffffffffu, ss, 8);
                    ws += __shfl_xor_sync(0xffffffffu, ws, 8);
                    ss += __shfl_xor_sync(0xffffffffu, ss, 16);
                    ws += __shfl_xor_sync(0xffffffffu, ws, 16);
                    if (g == 0) {
                        g_respre[(size_t)(p0 + ptl) * DIM + c + ci] = ws / ss;
                    }
                }
            }
        }
    }
}

// =======================================================================
extern "C" void kernel_launch(void* const* d_in, const int* in_sizes, int n_in,
                              void* d_out, int out_size) {
    const float* xyz_q    = (const float*)d_in[0];
    const float* feats_q  = (const float*)d_in[1];
    const float* xyz_kv   = (const float*)d_in[2];
    const float* feats_kv = (const float*)d_in[3];
    const float* Wq       = (const float*)d_in[4];
    const float* Wk       = (const float*)d_in[5];
    const float* Wv       = (const float*)d_in[6];
    const float* d1w      = (const float*)d_in[7];
    const float* d1b      = (const float*)d_in[8];
    const float* d2w      = (const float*)d_in[9];
    const float* d2b      = (const float*)d_in[10];
    const float* g1w      = (const float*)d_in[11];
    const float* g1b      = (const float*)d_in[12];
    const float* g2w      = (const float*)d_in[13];
    const float* g2b      = (const float*)d_in[14];
    const float* ow       = (const float*)d_in[15];
    const float* obias    = (const float*)d_in[16];
    float* out = (float*)d_out;

    long long ofs = (long long)out_size - (long long)NPTS * DOUT;
    if (ofs < 0) ofs = 0;
    if (ofs > 0)
        copy_xyz_kernel<<<(int)((ofs + 255) / 256), 256>>>(xyz_q, out, (int)ofs);

    convert_all<<<1152, 256>>>(Wk, Wv, g1w, g2w, d2w);

    qproj_kernel<<<NPTS / 32, 256>>>(feats_q, Wq);

    cudaFuncSetAttribute(fused_mma, cudaFuncAttributeMaxDynamicSharedMemorySize, SMEM_FUSED);
    fused_mma<<<NPTS / 2, 256, SMEM_FUSED>>>(xyz_q, xyz_kv, feats_kv,
                                             d1w, d1b, d2b, g1b, g2b);

    outproj_kernel<<<NPTS / 16, 256>>>(ow, obias, out, ofs);
}

// round 7
// speedup vs baseline: 1.2995x; 1.2995x over previous
#include <cuda_runtime.h>
#include <cuda_fp16.h>
#include <cstdint>

#define NPTS 8192
#define KN   32
#define DIM  256
#define DOUT 512
#define LDT  36
#define NTILES 4096      // m-tiles of 64 rows over M = NPTS*KN = 262144
#define GRID1 152        // GB300: 152 SMs

// ---------------- device scratch (allocation-free rule) ----------------
__device__ float  g_qattn[NPTS * DIM];
__device__ float  g_respre[NPTS * DIM];
__device__ __half g_bufA[(size_t)NPTS * KN * DIM];  // F16, later reused as A1
__device__ __half g_pe  [(size_t)NPTS * KN * DIM];
__device__ __half g_h   [(size_t)NPTS * KN * DIM];
__device__ __half g_vpe [(size_t)NPTS * KN * DIM];
// weights in ldmatrix-blocked layout (see boff)
__device__ __half g_WkB[DIM * DIM];   // -Wk
__device__ __half g_WvB[DIM * DIM];
__device__ __half g_g1B[DIM * DIM];
__device__ __half g_g2B[DIM * DIM];
__device__ __half g_d2B[DIM * 128];

// blocked half-index for weight element (n out-col, k in-row)
__device__ __forceinline__ int boff(int n, int k) {
    return ((k >> 4) * 8192 + (n >> 3) * 256 + ((k >> 3) & 1) * 128 +
            (n & 7) * 16 + (k & 7) * 2) >> 1;
}

extern "C" __global__ void convert_all(const float* __restrict__ Wk,
                                       const float* __restrict__ Wv,
                                       const float* __restrict__ g1w,
                                       const float* __restrict__ g2w,
                                       const float* __restrict__ d2w) {
    int idx = blockIdx.x * 256 + threadIdx.x;
    if (idx < 65536) {
        int k = idx >> 8, n = idx & 255;
        g_WkB[boff(n, k)] = __float2half(-Wk[k * 256 + n]);
    } else if (idx < 131072) {
        int i = idx - 65536; int k = i >> 8, n = i & 255;
        g_WvB[boff(n, k)] = __float2half(Wv[k * 256 + n]);
    } else if (idx < 196608) {
        int i = idx - 131072; int k = i >> 8, n = i & 255;
        g_g1B[boff(n, k)] = __float2half(g1w[k * 256 + n]);
    } else if (idx < 262144) {
        int i = idx - 196608; int k = i >> 8, n = i & 255;
        g_g2B[boff(n, k)] = __float2half(g2w[k * 256 + n]);
    } else if (idx < 294912) {
        int i = idx - 262144; int k = i >> 8, n = i & 255;   // k < 128
        g_d2B[boff(n, k)] = __float2half(d2w[k * 256 + n]);
    }
}

extern "C" __global__ void copy_xyz_kernel(const float* __restrict__ src,
                                           float* __restrict__ dst, int n) {
    int i = blockIdx.x * blockDim.x + threadIdx.x;
    if (i < n) dst[i] = src[i];
}

// ---------------- fp32 column-GEMM (q / out projections) -------
union F2U { float2 f; unsigned long long u; };
__device__ __forceinline__ void ffma2(float2& d, const float2 a, const float2 b) {
    F2U du, au, bu; du.f = d; au.f = a; bu.f = b;
    asm("fma.rn.f32x2 %0, %1, %2, %0;" : "+l"(du.u) : "l"(au.u), "l"(bu.u));
    d = du.f;
}
template <int KK, int NC>
__device__ __forceinline__ void colgemm(const float* __restrict__ At,
                                        const float* __restrict__ W,
                                        int c, float2 (&acc)[16]) {
#pragma unroll 4
    for (int kk = 0; kk < KK; ++kk) {
        float w = __ldg(W + kk * NC + c);
        float2 w2 = make_float2(w, w);
        const float4* a4 = reinterpret_cast<const float4*>(At + kk * LDT);
#pragma unroll
        for (int i = 0; i < 8; ++i) {
            float4 a = a4[i];
            ffma2(acc[2 * i],     make_float2(a.x, a.y), w2);
            ffma2(acc[2 * i + 1], make_float2(a.z, a.w), w2);
        }
    }
}

extern "C" __global__ void __launch_bounds__(256)
qproj_kernel(const float* __restrict__ feats_q, const float* __restrict__ Wq) {
    __shared__ float At[DIM * LDT];
    const int n0 = blockIdx.x * 32;
    const int f = threadIdx.x;
#pragma unroll
    for (int r = 0; r < 32; ++r) {
        At[f * LDT + r] = feats_q[(size_t)(n0 + r) * DIM + f];
    }
    __syncthreads();
    float2 acc[16];
#pragma unroll
    for (int i = 0; i < 16; ++i) { acc[i] = make_float2(0.f, 0.f); }
    colgemm<DIM, DIM>(At, Wq, f, acc);
#pragma unroll
    for (int i = 0; i < 16; ++i) {
        g_qattn[(size_t)(n0 + 2 * i) * DIM + f]     = acc[i].x;
        g_qattn[(size_t)(n0 + 2 * i + 1) * DIM + f] = acc[i].y;
    }
}

extern "C" __global__ void __launch_bounds__(256)
outproj_kernel(const float* __restrict__ ow, const float* __restrict__ ob,
               float* __restrict__ out, long long ofs) {
    __shared__ float At[DIM * LDT];
    const int n0 = (blockIdx.x >> 1) * 32;
    const int half = blockIdx.x & 1;
    const int t = threadIdx.x;
#pragma unroll
    for (int r = 0; r < 32; ++r) {
        At[t * LDT + r] = g_respre[(size_t)(n0 + r) * DIM + t];
    }
    __syncthreads();
    const int c = half * 256 + t;
    float2 acc[16];
    float b = ob[c];
#pragma unroll
    for (int i = 0; i < 16; ++i) { acc[i] = make_float2(b, b); }
    colgemm<DIM, DOUT>(At, ow, c, acc);
    float* dst = out + ofs;
#pragma unroll
    for (int i = 0; i < 16; ++i) {
        dst[(size_t)(n0 + 2 * i) * DOUT + c]     = acc[i].x;
        dst[(size_t)(n0 + 2 * i + 1) * DOUT + c] = acc[i].y;
    }
}

// =======================================================================
// Streaming weight-stationary GEMM machinery
// =======================================================================
__device__ __forceinline__ unsigned int swz(unsigned int row, unsigned int cb,
                                            unsigned int rb) {
    return row * rb + (cb ^ ((row & 7u) << 4));
}
__device__ __forceinline__ void cp_async16(unsigned int dst, const void* src) {
    asm volatile("cp.async.cg.shared.global [%0], [%1], 16;\n" :: "r"(dst), "l"(src) : "memory");
}
#define CP_COMMIT() asm volatile("cp.async.commit_group;\n" ::: "memory")
#define CP_WAIT(n)  asm volatile("cp.async.wait_group %0;\n" :: "n"(n) : "memory")

// stage a 64-row x 256-col fp16 tile (32KB) into swizzled smem (512B rows)
__device__ __forceinline__ void stage_tile(unsigned int dstb,
                                           const __half* __restrict__ src,
                                           size_t row0, int tid) {
#pragma unroll
    for (int i = 0; i < 4; ++i) {
        int c = tid + i * 512;
        unsigned int row = (unsigned int)(c >> 5);
        unsigned int c16 = (unsigned int)(c & 31) * 16u;
        cp_async16(dstb + swz(row, c16, 512u),
                   (const char*)(src + (row0 + row) * 256) + c16);
    }
}

// warp m32n32 tile: NSTEPS k16 steps, A swizzled smem (row-bytes arb),
// B resident smem in blocked layout with kstep stride kss.
template <int NSTEPS>
__device__ __forceinline__ void compute_tile(float (&acc)[2][4][4],
                                             unsigned int Abase, unsigned int arb,
                                             unsigned int Wbase, unsigned int kss,
                                             int lane, int wm, int wnl) {
    const int lr  = (lane & 7) + ((lane >> 3) & 1) * 8;
    const int lcb = ((lane >> 4) & 1) * 16;
    const int ntp = (lane >> 4) & 1;
    const int kh  = (lane >> 3) & 1;
    const int rr  = lane & 7;
#pragma unroll 4
    for (int ks = 0; ks < NSTEPS; ++ks) {
        unsigned int bf[2][4];
#pragma unroll
        for (int bg = 0; bg < 2; ++bg) {
            unsigned int ba = Wbase + (unsigned int)ks * kss
                            + (unsigned int)((wnl * 4 + bg * 2 + ntp) * 256 + kh * 128 + rr * 16);
            asm volatile("ldmatrix.sync.aligned.m8n8.x4.shared.b16 {%0,%1,%2,%3}, [%4];\n"
                         : "=r"(bf[bg][0]), "=r"(bf[bg][1]), "=r"(bf[bg][2]), "=r"(bf[bg][3])
                         : "r"(ba));
        }
#pragma unroll
        for (int mt = 0; mt < 2; ++mt) {
            unsigned int a0, a1, a2, a3;
            unsigned int ad = Abase + swz((unsigned int)(wm * 32 + mt * 16 + lr),
                                          (unsigned int)(ks * 32 + lcb), arb);
            asm volatile("ldmatrix.sync.aligned.m8n8.x4.shared.b16 {%0,%1,%2,%3}, [%4];\n"
                         : "=r"(a0), "=r"(a1), "=r"(a2), "=r"(a3) : "r"(ad));
#pragma unroll
            for (int nt = 0; nt < 4; ++nt) {
                asm volatile(
                    "mma.sync.aligned.m16n8k16.row.col.f32.f16.f16.f32 "
                    "{%0,%1,%2,%3},{%4,%5,%6,%7},{%8,%9},{%0,%1,%2,%3};\n"
                    : "+f"(acc[mt][nt][0]), "+f"(acc[mt][nt][1]),
                      "+f"(acc[mt][nt][2]), "+f"(acc[mt][nt][3])
                    : "r"(a0), "r"(a1), "r"(a2), "r"(a3),
                      "r"(bf[nt >> 1][(nt & 1) * 2]), "r"(bf[nt >> 1][(nt & 1) * 2 + 1]));
            }
        }
    }
}

#define ZERO_ACC(acc) \
    _Pragma("unroll") for (int _m = 0; _m < 2; ++_m) { \
    _Pragma("unroll") for (int _n = 0; _n < 4; ++_n) { \
    _Pragma("unroll") for (int _i = 0; _i < 4; ++_i) { acc[_m][_n][_i] = 0.f; } } }

// =======================================================================
// K1: F fp32->fp16 conversion + H1 pos-MLP + pe = H1 @ d2 (d2 resident)
// smem: d2B 64KB @0, H1 16KB @65536
// =======================================================================
extern "C" __global__ void __launch_bounds__(512, 1)
stage_pe(const float* __restrict__ xyz_q, const float* __restrict__ xyz_kv,
         const float* __restrict__ feats_kv,
         const float* __restrict__ d1w, const float* __restrict__ d1b) {
    extern __shared__ char smem[];
    const unsigned int smb = (unsigned int)__cvta_generic_to_shared(smem);
    const int tid  = threadIdx.x;
    const int lane = tid & 31;
    const int wid  = tid >> 5;
    const int wm   = (wid >> 3) & 1, wnl = wid & 7;
    const int g    = lane >> 2, tig = lane & 3;

    // stage d2 weights (64KB linear, blocked layout identical in smem)
    for (int i = tid; i < 4096; i += 512) {
        cp_async16(smb + (unsigned int)(i * 16), (const char*)g_d2B + i * 16);
    }
    CP_COMMIT(); CP_WAIT(0);
    __syncthreads();

    for (int t = blockIdx.x; t < NTILES; t += GRID1) {
        // F conversion: rows [t*64, t*64+64), fp32 -> fp16 global
        {
            const float4* fs = (const float4*)feats_kv;
#pragma unroll
            for (int i0 = 0; i0 < 8; ++i0) {
                int i = tid + i0 * 512;
                int row = i >> 6, c4 = i & 63;
                size_t grow = (size_t)t * 64 + row;
                float4 v = __ldg(fs + grow * 64 + c4);
                __half2 h01 = __floats2half2_rn(v.x, v.y);
                __half2 h23 = __floats2half2_rn(v.z, v.w);
                uint2 u = make_uint2(*(unsigned int*)&h01, *(unsigned int*)&h23);
                *(uint2*)(g_bufA + grow * 256 + c4 * 4) = u;
            }
        }
        __syncthreads();   // previous iteration's gemm done reading H1
        // H1 = relu(rel @ d1 + b): 64 x 128 into smem (256B rows swizzled)
        {
            unsigned int row = (unsigned int)(tid >> 3);
            int cb = (tid & 7) * 16;
            int p = (int)(row >> 5), k = (int)(row & 31);
            int pt = t * 2 + p;
            float qx = __ldg(xyz_q + pt * 3 + 0);
            float qy = __ldg(xyz_q + pt * 3 + 1);
            float qz = __ldg(xyz_q + pt * 3 + 2);
            const float* pk = xyz_kv + ((size_t)pt * KN + k) * 3;
            float rx = qx - __ldg(pk + 0), ry = qy - __ldg(pk + 1), rz = qz - __ldg(pk + 2);
#pragma unroll 4
            for (int c = cb; c < cb + 16; c += 2) {
                float h0 = fmaf(rx, __ldg(d1w + c),     fmaf(ry, __ldg(d1w + 128 + c),     fmaf(rz, __ldg(d1w + 256 + c),     __ldg(d1b + c))));
                float h1 = fmaf(rx, __ldg(d1w + c + 1), fmaf(ry, __ldg(d1w + 128 + c + 1), fmaf(rz, __ldg(d1w + 256 + c + 1), __ldg(d1b + c + 1))));
                __half2 hh = __floats2half2_rn(fmaxf(h0, 0.f), fmaxf(h1, 0.f));
                *(__half2*)(smem + 65536 + swz(row, (unsigned int)c * 2u, 256u)) = hh;
            }
        }
        __syncthreads();
        float acc[2][4][4];
        ZERO_ACC(acc);
        compute_tile<8>(acc, smb + 65536u, 256u, smb, 8192u, lane, wm, wnl);
        // store pe fp16 (no bias)
#pragma unroll
        for (int nt = 0; nt < 4; ++nt) {
            int c = wnl * 32 + nt * 8 + 2 * tig;
#pragma unroll
            for (int mt = 0; mt < 2; ++mt) {
                size_t r0 = (size_t)t * 64 + wm * 32 + mt * 16 + g;
                __half2 lo = __floats2half2_rn(acc[mt][nt][0], acc[mt][nt][1]);
                __half2 hi = __floats2half2_rn(acc[mt][nt][2], acc[mt][nt][3]);
                *(__half2*)(g_pe + r0 * 256 + c)       = lo;
                *(__half2*)(g_pe + (r0 + 8) * 256 + c) = hi;
            }
        }
    }
}

// =======================================================================
// AB: h = q + d2b + pe + F@(-Wk) ; vpe = d2b + pe + F@Wv
// CTA: n-half (128 cols) of both outputs; Wk/Wv halves resident (128KB),
// F tiles m64 double-buffered (2 x 32KB). grid = 304 (tile x nhalf).
// warps 0-7 -> h, warps 8-15 -> vpe; each 2m x 4n of m32n32.
// =======================================================================
extern "C" __global__ void __launch_bounds__(512, 1)
pass_ab(const float* __restrict__ d2b) {
    extern __shared__ char smem[];
    const unsigned int smb = (unsigned int)__cvta_generic_to_shared(smem);
    const int tid  = threadIdx.x;
    const int lane = tid & 31;
    const int wid  = tid >> 5;
    const int b    = blockIdx.x;
    const int nh   = b & 1;
    const int out  = wid >> 3;
    const int w8   = wid & 7;
    const int wm   = w8 >> 2, wnl = w8 & 3;
    const int g    = lane >> 2, tig = lane & 3;
    const unsigned int Wbase = smb + (unsigned int)out * 65536u;
    const unsigned int DB = smb + 131072u;

    // stage Wk/Wv n-halves (2 x 64KB)
    for (int i = tid; i < 8192; i += 512) {
        int w = i >> 12, c = i & 4095, ks = c >> 8, rem = c & 255;
        const char* srcb = (const char*)(w ? g_WvB : g_WkB) + ks * 8192 + nh * 4096 + rem * 16;
        cp_async16(smb + (unsigned int)(w * 65536 + ks * 4096 + rem * 16), srcb);
    }
    const int t0 = b >> 1;
    stage_tile(DB, g_bufA, (size_t)t0 * 64, tid);
    CP_COMMIT();

    int it = 0;
    for (int t = t0; t < NTILES; t += GRID1, ++it) {
        int tn = t + GRID1;
        if (tn < NTILES) {
            stage_tile(DB + ((it + 1) & 1) * 32768u, g_bufA, (size_t)tn * 64, tid);
            CP_COMMIT(); CP_WAIT(1);
        } else { CP_WAIT(0); }
        __syncthreads();
        float acc[2][4][4];
        ZERO_ACC(acc);
        compute_tile<16>(acc, DB + (it & 1) * 32768u, 512u, Wbase, 4096u, lane, wm, wnl);
        // epilogue
        __half* dstArr = out ? g_vpe : g_h;
        const float* qrow = g_qattn + (size_t)(t * 2 + wm) * DIM;
#pragma unroll
        for (int nt = 0; nt < 4; ++nt) {
            int c = nh * 128 + wnl * 32 + nt * 8 + 2 * tig;
            float a0 = __ldg(d2b + c), a1 = __ldg(d2b + c + 1);
            if (out == 0) { a0 += __ldg(qrow + c); a1 += __ldg(qrow + c + 1); }
#pragma unroll
            for (int mt = 0; mt < 2; ++mt) {
                size_t r0 = (size_t)t * 64 + wm * 32 + mt * 16 + g;
                float2 pl = __half22float2(*(const __half2*)(g_pe + r0 * 256 + c));
                float2 ph = __half22float2(*(const __half2*)(g_pe + (r0 + 8) * 256 + c));
                __half2 lo = __floats2half2_rn(acc[mt][nt][0] + a0 + pl.x,
                                               acc[mt][nt][1] + a1 + pl.y);
                __half2 hi = __floats2half2_rn(acc[mt][nt][2] + a0 + ph.x,
                                               acc[mt][nt][3] + a1 + ph.y);
                *(__half2*)(dstArr + r0 * 256 + c)       = lo;
                *(__half2*)(dstArr + (r0 + 8) * 256 + c) = hi;
            }
        }
        __syncthreads();
    }
}

// =======================================================================
// C: A1 = relu(h @ g1 + g1b) -> g_bufA. g1 full-N resident (128KB).
// warps 2m x 8n of m32n32. grid = 152.
// =======================================================================
extern "C" __global__ void __launch_bounds__(512, 1)
pass_c(const float* __restrict__ g1b) {
    extern __shared__ char smem[];
    const unsigned int smb = (unsigned int)__cvta_generic_to_shared(smem);
    const int tid  = threadIdx.x;
    const int lane = tid & 31;
    const int wid  = tid >> 5;
    const int wm   = (wid >> 3) & 1, wnl = wid & 7;
    const int g    = lane >> 2, tig = lane & 3;
    const unsigned int DB = smb + 131072u;

    for (int i = tid; i < 8192; i += 512) {
        cp_async16(smb + (unsigned int)(i * 16), (const char*)g_g1B + i * 16);
    }
    const int t0 = blockIdx.x;
    stage_tile(DB, g_h, (size_t)t0 * 64, tid);
    CP_COMMIT();

    int it = 0;
    for (int t = t0; t < NTILES; t += GRID1, ++it) {
        int tn = t + GRID1;
        if (tn < NTILES) {
            stage_tile(DB + ((it + 1) & 1) * 32768u, g_h, (size_t)tn * 64, tid);
            CP_COMMIT(); CP_WAIT(1);
        } else { CP_WAIT(0); }
        __syncthreads();
        float acc[2][4][4];
        ZERO_ACC(acc);
        compute_tile<16>(acc, DB + (it & 1) * 32768u, 512u, smb, 8192u, lane, wm, wnl);
#pragma unroll
        for (int nt = 0; nt < 4; ++nt) {
            int c = wnl * 32 + nt * 8 + 2 * tig;
            float b0 = __ldg(g1b + c), b1 = __ldg(g1b + c + 1);
#pragma unroll
            for (int mt = 0; mt < 2; ++mt) {
                size_t r0 = (size_t)t * 64 + wm * 32 + mt * 16 + g;
                __half2 lo = __floats2half2_rn(fmaxf(acc[mt][nt][0] + b0, 0.f),
                                               fmaxf(acc[mt][nt][1] + b1, 0.f));
                __half2 hi = __floats2half2_rn(fmaxf(acc[mt][nt][2] + b0, 0.f),
                                               fmaxf(acc[mt][nt][3] + b1, 0.f));
                *(__half2*)(g_bufA + r0 * 256 + c)       = lo;
                *(__half2*)(g_bufA + (r0 + 8) * 256 + c) = hi;
            }
        }
        __syncthreads();
    }
}

// =======================================================================
// D: logits = A1 @ g2 + g2b ; softmax over 32 neighbors; res -> g_respre
// g2 full-N resident. warp m32 block = exactly one point's 32 neighbors.
// =======================================================================
extern "C" __global__ void __launch_bounds__(512, 1)
pass_d(const float* __restrict__ g2b) {
    extern __shared__ char smem[];
    const unsigned int smb = (unsigned int)__cvta_generic_to_shared(smem);
    const int tid  = threadIdx.x;
    const int lane = tid & 31;
    const int wid  = tid >> 5;
    const int wm   = (wid >> 3) & 1, wnl = wid & 7;
    const int g    = lane >> 2, tig = lane & 3;
    const unsigned int DB = smb + 131072u;

    for (int i = tid; i < 8192; i += 512) {
        cp_async16(smb + (unsigned int)(i * 16), (const char*)g_g2B + i * 16);
    }
    const int t0 = blockIdx.x;
    stage_tile(DB, g_bufA, (size_t)t0 * 64, tid);
    CP_COMMIT();

    int it = 0;
    for (int t = t0; t < NTILES; t += GRID1, ++it) {
        int tn = t + GRID1;
        if (tn < NTILES) {
            stage_tile(DB + ((it + 1) & 1) * 32768u, g_bufA, (size_t)tn * 64, tid);
            CP_COMMIT(); CP_WAIT(1);
        } else { CP_WAIT(0); }
        __syncthreads();
        float acc[2][4][4];
        ZERO_ACC(acc);
        compute_tile<16>(acc, DB + (it & 1) * 32768u, 512u, smb, 8192u, lane, wm, wnl);
        // softmax epilogue: point = t*2 + wm, rows {g, g+8, 16+g, 24+g}
        const size_t rb = (size_t)t * 64 + wm * 32;
#pragma unroll
        for (int nt = 0; nt < 4; ++nt) {
            int c = wnl * 32 + nt * 8 + 2 * tig;
            float gb0 = __ldg(g2b + c), gb1 = __ldg(g2b + c + 1);
            float2 v00 = __half22float2(*(const __half2*)(g_vpe + (rb + g) * 256 + c));
            float2 v01 = __half22float2(*(const __half2*)(g_vpe + (rb + 8 + g) * 256 + c));
            float2 v10 = __half22float2(*(const __half2*)(g_vpe + (rb + 16 + g) * 256 + c));
            float2 v11 = __half22float2(*(const __half2*)(g_vpe + (rb + 24 + g) * 256 + c));
#pragma unroll
            for (int ci = 0; ci < 2; ++ci) {
                float gb = ci ? gb1 : gb0;
                float l0 = acc[0][nt][ci]     + gb;
                float l1 = acc[0][nt][ci + 2] + gb;
                float l2 = acc[1][nt][ci]     + gb;
                float l3 = acc[1][nt][ci + 2] + gb;
                float v0 = ci ? v00.y : v00.x;
                float v1 = ci ? v01.y : v01.x;
                float v2 = ci ? v10.y : v10.x;
                float v3 = ci ? v11.y : v11.x;
                float mx = fmaxf(fmaxf(l0, l1), fmaxf(l2, l3));
                mx = fmaxf(mx, __shfl_xor_sync(0xffffffffu, mx, 4));
                mx = fmaxf(mx, __shfl_xor_sync(0xffffffffu, mx, 8));
                mx = fmaxf(mx, __shfl_xor_sync(0xffffffffu, mx, 16));
                float e0 = __expf(l0 - mx), e1 = __expf(l1 - mx);
                float e2 = __expf(l2 - mx), e3 = __expf(l3 - mx);
                float ss = (e0 + e1) + (e2 + e3);
                float ws = (e0 * v0 + e1 * v1) + (e2 * v2 + e3 * v3);
                ss += __shfl_xor_sync(0xffffffffu, ss, 4);
                ws += __shfl_xor_sync(0xffffffffu, ws, 4);
                ss += __shfl_xor_sync(0xffffffffu, ss, 8);
                ws += __shfl_xor_sync(0xffffffffu, ws, 8);
                ss += __shfl_xor_sync(0xffffffffu, ss, 16);
                ws += __shfl_xor_sync(0xffffffffu, ws, 16);
                if (g == 0) {
                    g_respre[(size_t)(t * 2 + wm) * DIM + c + ci] = ws / ss;
                }
            }
        }
        __syncthreads();
    }
}

// =======================================================================
extern "C" void kernel_launch(void* const* d_in, const int* in_sizes, int n_in,
                              void* d_out, int out_size) {
    const float* xyz_q    = (const float*)d_in[0];
    const float* feats_q  = (const float*)d_in[1];
    const float* xyz_kv   = (const float*)d_in[2];
    const float* feats_kv = (const float*)d_in[3];
    const float* Wq       = (const float*)d_in[4];
    const float* Wk       = (const float*)d_in[5];
    const float* Wv       = (const float*)d_in[6];
    const float* d1w      = (const float*)d_in[7];
    const float* d1b      = (const float*)d_in[8];
    const float* d2w      = (const float*)d_in[9];
    const float* d2b      = (const float*)d_in[10];
    const float* g1w      = (const float*)d_in[11];
    const float* g1b      = (const float*)d_in[12];
    const float* g2w      = (const float*)d_in[13];
    const float* g2b      = (const float*)d_in[14];
    const float* ow       = (const float*)d_in[15];
    const float* obias    = (const float*)d_in[16];
    float* out = (float*)d_out;

    long long ofs = (long long)out_size - (long long)NPTS * DOUT;
    if (ofs < 0) ofs = 0;
    if (ofs > 0)
        copy_xyz_kernel<<<(int)((ofs + 255) / 256), 256>>>(xyz_q, out, (int)ofs);

    convert_all<<<1152, 256>>>(Wk, Wv, g1w, g2w, d2w);
    qproj_kernel<<<NPTS / 32, 256>>>(feats_q, Wq);

    cudaFuncSetAttribute(stage_pe, cudaFuncAttributeMaxDynamicSharedMemorySize, 81920);
    cudaFuncSetAttribute(pass_ab,  cudaFuncAttributeMaxDynamicSharedMemorySize, 196608);
    cudaFuncSetAttribute(pass_c,   cudaFuncAttributeMaxDynamicSharedMemorySize, 196608);
    cudaFuncSetAttribute(pass_d,   cudaFuncAttributeMaxDynamicSharedMemorySize, 196608);

    stage_pe<<<GRID1, 512, 81920>>>(xyz_q, xyz_kv, feats_kv, d1w, d1b);
    pass_ab<<<2 * GRID1, 512, 196608>>>(d2b);
    pass_c<<<GRID1, 512, 196608>>>(g1b);
    pass_d<<<GRID1, 512, 196608>>>(g2b);

    outproj_kernel<<<NPTS / 16, 256>>>(ow, obias, out, ofs);
}

// round 8
// speedup vs baseline: 1.4261x; 1.0975x over previous
#include <cuda_runtime.h>
#include <cuda_fp16.h>
#include <cstdint>

#define NPTS 8192
#define KN   32
#define DIM  256
#define DOUT 512
#define NTILES 4096      // m64 tiles over M = NPTS*KN = 262144
#define NQTILES 128      // m64 tiles over NPTS = 8192
#define GRID1 152

// ---------------- device scratch (allocation-free rule) ----------------
__device__ float  g_qattn[NPTS * DIM];
__device__ __half g_fq16[NPTS * DIM];
__device__ __half g_res16[NPTS * DIM];
__device__ __half g_bufA[(size_t)NPTS * KN * DIM];  // F16, later A1
__device__ __half g_pe  [(size_t)NPTS * KN * DIM];
__device__ __half g_h   [(size_t)NPTS * KN * DIM];
__device__ __half g_vpe [(size_t)NPTS * KN * DIM];
// weights, ldmatrix-blocked
__device__ __half g_WkB[DIM * DIM];   // -Wk
__device__ __half g_WvB[DIM * DIM];
__device__ __half g_g1B[DIM * DIM];
__device__ __half g_g2B[DIM * DIM];
__device__ __half g_d2B[DIM * 128];
__device__ __half g_WqB[DIM * DIM];
__device__ __half g_owB[DIM * DOUT];

__device__ __forceinline__ int boff(int n, int k) {
    return ((k >> 4) * 8192 + (n >> 3) * 256 + ((k >> 3) & 1) * 128 +
            (n & 7) * 16 + (k & 7) * 2) >> 1;
}
__device__ __forceinline__ int boff512(int n, int k) {
    return ((k >> 4) * 16384 + (n >> 3) * 256 + ((k >> 3) & 1) * 128 +
            (n & 7) * 16 + (k & 7) * 2) >> 1;
}

extern "C" __global__ void convert_all(const float* __restrict__ Wk,
                                       const float* __restrict__ Wv,
                                       const float* __restrict__ g1w,
                                       const float* __restrict__ g2w,
                                       const float* __restrict__ d2w,
                                       const float* __restrict__ Wq,
                                       const float* __restrict__ ow) {
    int idx = blockIdx.x * 256 + threadIdx.x;
    if (idx < 65536) {
        int k = idx >> 8, n = idx & 255;
        g_WkB[boff(n, k)] = __float2half(-Wk[k * 256 + n]);
    } else if (idx < 131072) {
        int i = idx - 65536; int k = i >> 8, n = i & 255;
        g_WvB[boff(n, k)] = __float2half(Wv[k * 256 + n]);
    } else if (idx < 196608) {
        int i = idx - 131072; int k = i >> 8, n = i & 255;
        g_g1B[boff(n, k)] = __float2half(g1w[k * 256 + n]);
    } else if (idx < 262144) {
        int i = idx - 196608; int k = i >> 8, n = i & 255;
        g_g2B[boff(n, k)] = __float2half(g2w[k * 256 + n]);
    } else if (idx < 294912) {
        int i = idx - 262144; int k = i >> 8, n = i & 255;   // k < 128
        g_d2B[boff(n, k)] = __float2half(d2w[k * 256 + n]);
    } else if (idx < 360448) {
        int i = idx - 294912; int k = i >> 8, n = i & 255;
        g_WqB[boff(n, k)] = __float2half(Wq[k * 256 + n]);
    } else if (idx < 491520) {
        int i = idx - 360448; int k = i >> 9, n = i & 511;
        g_owB[boff512(n, k)] = __float2half(ow[k * 512 + n]);
    }
}

// pure-BW fp32 -> fp16 conversion of feats_kv and feats_q
extern "C" __global__ void __launch_bounds__(256)
convert_inputs(const float* __restrict__ feats_kv, const float* __restrict__ feats_q) {
    size_t idx = (size_t)blockIdx.x * 256 + threadIdx.x;
    const size_t KV8 = (size_t)NPTS * KN * DIM / 8;   // 8388608
    const size_t Q8  = (size_t)NPTS * DIM / 8;        // 262144
    const float4* src; __half* dst; size_t e;
    if (idx < KV8)           { src = (const float4*)feats_kv; dst = g_bufA; e = idx * 2; }
    else if (idx < KV8 + Q8) { src = (const float4*)feats_q;  dst = g_fq16; e = (idx - KV8) * 2; }
    else return;
    float4 a = __ldg(src + e), b = __ldg(src + e + 1);
    __half2 h0 = __floats2half2_rn(a.x, a.y), h1 = __floats2half2_rn(a.z, a.w);
    __half2 h2 = __floats2half2_rn(b.x, b.y), h3 = __floats2half2_rn(b.z, b.w);
    uint4 u = make_uint4(*(unsigned int*)&h0, *(unsigned int*)&h1,
                         *(unsigned int*)&h2, *(unsigned int*)&h3);
    *(uint4*)(dst + e * 4) = u;
}

extern "C" __global__ void copy_xyz_kernel(const float* __restrict__ src,
                                           float* __restrict__ dst, int n) {
    int i = blockIdx.x * blockDim.x + threadIdx.x;
    if (i < n) dst[i] = src[i];
}

// =======================================================================
// streaming mma machinery
// =======================================================================
__device__ __forceinline__ unsigned int swz(unsigned int row, unsigned int cb,
                                            unsigned int rb) {
    return row * rb + (cb ^ ((row & 7u) << 4));
}
__device__ __forceinline__ void cp_async16(unsigned int dst, const void* src) {
    asm volatile("cp.async.cg.shared.global [%0], [%1], 16;\n" :: "r"(dst), "l"(src) : "memory");
}
#define CP_COMMIT() asm volatile("cp.async.commit_group;\n" ::: "memory")
#define CP_WAIT(n)  asm volatile("cp.async.wait_group %0;\n" :: "n"(n) : "memory")

// stage a 64-row x 256-col fp16 tile (32KB) into swizzled smem (512 threads)
__device__ __forceinline__ void stage_tile(unsigned int dstb,
                                           const __half* __restrict__ src,
                                           size_t row0, int tid) {
#pragma unroll
    for (int i = 0; i < 4; ++i) {
        int c = tid + i * 512;
        unsigned int row = (unsigned int)(c >> 5);
        unsigned int c16 = (unsigned int)(c & 31) * 16u;
        cp_async16(dstb + swz(row, c16, 512u),
                   (const char*)(src + (row0 + row) * 256) + c16);
    }
}

template <int NSTEPS>
__device__ __forceinline__ void compute_tile(float (&acc)[2][4][4],
                                             unsigned int Abase, unsigned int arb,
                                             unsigned int Wbase, unsigned int kss,
                                             int lane, int wm, int wnl) {
    const int lr  = (lane & 7) + ((lane >> 3) & 1) * 8;
    const int lcb = ((lane >> 4) & 1) * 16;
    const int ntp = (lane >> 4) & 1;
    const int kh  = (lane >> 3) & 1;
    const int rr  = lane & 7;
#pragma unroll 4
    for (int ks = 0; ks < NSTEPS; ++ks) {
        unsigned int bf[2][4];
#pragma unroll
        for (int bg = 0; bg < 2; ++bg) {
            unsigned int ba = Wbase + (unsigned int)ks * kss
                            + (unsigned int)((wnl * 4 + bg * 2 + ntp) * 256 + kh * 128 + rr * 16);
            asm volatile("ldmatrix.sync.aligned.m8n8.x4.shared.b16 {%0,%1,%2,%3}, [%4];\n"
                         : "=r"(bf[bg][0]), "=r"(bf[bg][1]), "=r"(bf[bg][2]), "=r"(bf[bg][3])
                         : "r"(ba));
        }
#pragma unroll
        for (int mt = 0; mt < 2; ++mt) {
            unsigned int a0, a1, a2, a3;
            unsigned int ad = Abase + swz((unsigned int)(wm * 32 + mt * 16 + lr),
                                          (unsigned int)(ks * 32 + lcb), arb);
            asm volatile("ldmatrix.sync.aligned.m8n8.x4.shared.b16 {%0,%1,%2,%3}, [%4];\n"
                         : "=r"(a0), "=r"(a1), "=r"(a2), "=r"(a3) : "r"(ad));
#pragma unroll
            for (int nt = 0; nt < 4; ++nt) {
                asm volatile(
                    "mma.sync.aligned.m16n8k16.row.col.f32.f16.f16.f32 "
                    "{%0,%1,%2,%3},{%4,%5,%6,%7},{%8,%9},{%0,%1,%2,%3};\n"
                    : "+f"(acc[mt][nt][0]), "+f"(acc[mt][nt][1]),
                      "+f"(acc[mt][nt][2]), "+f"(acc[mt][nt][3])
                    : "r"(a0), "r"(a1), "r"(a2), "r"(a3),
                      "r"(bf[nt >> 1][(nt & 1) * 2]), "r"(bf[nt >> 1][(nt & 1) * 2 + 1]));
            }
        }
    }
}

#define ZERO_ACC(acc) \
    _Pragma("unroll") for (int _m = 0; _m < 2; ++_m) { \
    _Pragma("unroll") for (int _n = 0; _n < 4; ++_n) { \
    _Pragma("unroll") for (int _i = 0; _i < 4; ++_i) { acc[_m][_n][_i] = 0.f; } } }

// =======================================================================
// pe kernel: per point (m32), H1 = relu(rel@d1+b) in smem, pe = H1@d2.
// d2 resident 64KB + H1 8KB = 72KB -> 2 CTAs/SM of 256 threads.
// =======================================================================
extern "C" __global__ void __launch_bounds__(256, 2)
pe_kernel(const float* __restrict__ xyz_q, const float* __restrict__ xyz_kv,
          const float* __restrict__ d1w, const float* __restrict__ d1b) {
    extern __shared__ char smem[];
    const unsigned int smb = (unsigned int)__cvta_generic_to_shared(smem);
    const int tid  = threadIdx.x;
    const int lane = tid & 31;
    const int wnl  = tid >> 5;
    const int g    = lane >> 2, tig = lane & 3;

    for (int i = tid; i < 4096; i += 256) {
        cp_async16(smb + (unsigned int)(i * 16), (const char*)g_d2B + i * 16);
    }
    CP_COMMIT(); CP_WAIT(0);
    __syncthreads();

    const unsigned int H1 = smb + 65536u;
    for (int pt = blockIdx.x; pt < NPTS; pt += 2 * GRID1) {
        __syncthreads();  // previous gemm done reading H1
        {
            unsigned int row = (unsigned int)(tid >> 3);   // neighbor 0..31
            int cb = (tid & 7) * 16;
            float qx = __ldg(xyz_q + pt * 3 + 0);
            float qy = __ldg(xyz_q + pt * 3 + 1);
            float qz = __ldg(xyz_q + pt * 3 + 2);
            const float* pk = xyz_kv + ((size_t)pt * KN + row) * 3;
            float rx = qx - __ldg(pk + 0), ry = qy - __ldg(pk + 1), rz = qz - __ldg(pk + 2);
#pragma unroll 4
            for (int c = cb; c < cb + 16; c += 2) {
                float h0 = fmaf(rx, __ldg(d1w + c),     fmaf(ry, __ldg(d1w + 128 + c),     fmaf(rz, __ldg(d1w + 256 + c),     __ldg(d1b + c))));
                float h1 = fmaf(rx, __ldg(d1w + c + 1), fmaf(ry, __ldg(d1w + 128 + c + 1), fmaf(rz, __ldg(d1w + 256 + c + 1), __ldg(d1b + c + 1))));
                __half2 hh = __floats2half2_rn(fmaxf(h0, 0.f), fmaxf(h1, 0.f));
                *(__half2*)(smem + 65536 + swz(row, (unsigned int)c * 2u, 256u)) = hh;
            }
        }
        __syncthreads();
        float acc[2][4][4];
        ZERO_ACC(acc);
        compute_tile<8>(acc, H1, 256u, smb, 8192u, lane, 0, wnl);
#pragma unroll
        for (int nt = 0; nt < 4; ++nt) {
            int c = wnl * 32 + nt * 8 + 2 * tig;
#pragma unroll
            for (int mt = 0; mt < 2; ++mt) {
                size_t r0 = (size_t)pt * 32 + mt * 16 + g;
                __half2 lo = __floats2half2_rn(acc[mt][nt][0], acc[mt][nt][1]);
                __half2 hi = __floats2half2_rn(acc[mt][nt][2], acc[mt][nt][3]);
                *(__half2*)(g_pe + r0 * 256 + c)       = lo;
                *(__half2*)(g_pe + (r0 + 8) * 256 + c) = hi;
            }
        }
    }
}

// =======================================================================
// qproj: qattn = fq16 @ Wq (fp32 out). Wq resident 128KB + 1 tile. grid 128.
// =======================================================================
extern "C" __global__ void __launch_bounds__(512, 1)
qproj_mma() {
    extern __shared__ char smem[];
    const unsigned int smb = (unsigned int)__cvta_generic_to_shared(smem);
    const int tid  = threadIdx.x;
    const int lane = tid & 31;
    const int wid  = tid >> 5;
    const int wm   = (wid >> 3) & 1, wnl = wid & 7;
    const int g    = lane >> 2, tig = lane & 3;
    const int t    = blockIdx.x;

    for (int i = tid; i < 8192; i += 512) {
        cp_async16(smb + (unsigned int)(i * 16), (const char*)g_WqB + i * 16);
    }
    stage_tile(smb + 131072u, g_fq16, (size_t)t * 64, tid);
    CP_COMMIT(); CP_WAIT(0);
    __syncthreads();

    float acc[2][4][4];
    ZERO_ACC(acc);
    compute_tile<16>(acc, smb + 131072u, 512u, smb, 8192u, lane, wm, wnl);
#pragma unroll
    for (int nt = 0; nt < 4; ++nt) {
        int c = wnl * 32 + nt * 8 + 2 * tig;
#pragma unroll
        for (int mt = 0; mt < 2; ++mt) {
            size_t r0 = (size_t)t * 64 + wm * 32 + mt * 16 + g;
            g_qattn[r0 * 256 + c]           = acc[mt][nt][0];
            g_qattn[r0 * 256 + c + 1]       = acc[mt][nt][1];
            g_qattn[(r0 + 8) * 256 + c]     = acc[mt][nt][2];
            g_qattn[(r0 + 8) * 256 + c + 1] = acc[mt][nt][3];
        }
    }
}

// =======================================================================
// outproj: out = res16 @ ow + ob. ow n-half resident 128KB. grid 256.
// =======================================================================
extern "C" __global__ void __launch_bounds__(512, 1)
outproj_mma(const float* __restrict__ ob, float* __restrict__ out, long long ofs) {
    extern __shared__ char smem[];
    const unsigned int smb = (unsigned int)__cvta_generic_to_shared(smem);
    const int tid  = threadIdx.x;
    const int lane = tid & 31;
    const int wid  = tid >> 5;
    const int wm   = (wid >> 3) & 1, wnl = wid & 7;
    const int g    = lane >> 2, tig = lane & 3;
    const int t    = blockIdx.x >> 1;
    const int nh   = blockIdx.x & 1;

    for (int i = tid; i < 8192; i += 512) {
        int kb = i >> 9, rem = i & 511;
        cp_async16(smb + (unsigned int)(kb * 8192 + rem * 16),
                   (const char*)g_owB + kb * 16384 + nh * 8192 + rem * 16);
    }
    stage_tile(smb + 131072u, g_res16, (size_t)t * 64, tid);
    CP_COMMIT(); CP_WAIT(0);
    __syncthreads();

    float acc[2][4][4];
    ZERO_ACC(acc);
    compute_tile<16>(acc, smb + 131072u, 512u, smb, 8192u, lane, wm, wnl);
    float* dst = out + ofs;
#pragma unroll
    for (int nt = 0; nt < 4; ++nt) {
        int c = nh * 256 + wnl * 32 + nt * 8 + 2 * tig;
        float b0 = __ldg(ob + c), b1 = __ldg(ob + c + 1);
#pragma unroll
        for (int mt = 0; mt < 2; ++mt) {
            size_t r0 = (size_t)t * 64 + wm * 32 + mt * 16 + g;
            dst[r0 * 512 + c]           = acc[mt][nt][0] + b0;
            dst[r0 * 512 + c + 1]       = acc[mt][nt][1] + b1;
            dst[(r0 + 8) * 512 + c]     = acc[mt][nt][2] + b0;
            dst[(r0 + 8) * 512 + c + 1] = acc[mt][nt][3] + b1;
        }
    }
}

// =======================================================================
// AB: h = q + d2b + pe + F@(-Wk) ; vpe = d2b + pe + F@Wv
// Wk/Wv n-halves resident 128KB, 3-deep 32KB data buffers. grid 304.
// =======================================================================
extern "C" __global__ void __launch_bounds__(512, 1)
pass_ab(const float* __restrict__ d2b) {
    extern __shared__ char smem[];
    const unsigned int smb = (unsigned int)__cvta_generic_to_shared(smem);
    const int tid  = threadIdx.x;
    const int lane = tid & 31;
    const int wid  = tid >> 5;
    const int b    = blockIdx.x;
    const int nh   = b & 1;
    const int out  = wid >> 3;
    const int w8   = wid & 7;
    const int wm   = w8 >> 2, wnl = w8 & 3;
    const int g    = lane >> 2, tig = lane & 3;
    const unsigned int Wbase = smb + (unsigned int)out * 65536u;
    const unsigned int DB = smb + 131072u;

    for (int i = tid; i < 8192; i += 512) {
        int w = i >> 12, c = i & 4095, ks = c >> 8, rem = c & 255;
        const char* srcb = (const char*)(w ? g_WvB : g_WkB) + ks * 8192 + nh * 4096 + rem * 16;
        cp_async16(smb + (unsigned int)(w * 65536 + ks * 4096 + rem * 16), srcb);
    }
    const int t0 = b >> 1;
    stage_tile(DB, g_bufA, (size_t)t0 * 64, tid);
    CP_COMMIT();
    if (t0 + GRID1 < NTILES) {
        stage_tile(DB + 32768u, g_bufA, (size_t)(t0 + GRID1) * 64, tid);
        CP_COMMIT();
    }

    int it = 0;
    for (int t = t0; t < NTILES; t += GRID1, ++it) {
        if (t + GRID1 < NTILES) { CP_WAIT(1); } else { CP_WAIT(0); }
        __syncthreads();
        int t2 = t + 2 * GRID1;
        if (t2 < NTILES) {
            stage_tile(DB + (unsigned int)((it + 2) % 3) * 32768u, g_bufA, (size_t)t2 * 64, tid);
            CP_COMMIT();
        }
        float acc[2][4][4];
        ZERO_ACC(acc);
        compute_tile<16>(acc, DB + (unsigned int)(it % 3) * 32768u, 512u, Wbase, 4096u, lane, wm, wnl);
        __half* dstArr = out ? g_vpe : g_h;
        const float* qrow = g_qattn + (size_t)(t * 2 + wm) * DIM;
#pragma unroll
        for (int nt = 0; nt < 4; ++nt) {
            int c = nh * 128 + wnl * 32 + nt * 8 + 2 * tig;
            float a0 = __ldg(d2b + c), a1 = __ldg(d2b + c + 1);
            if (out == 0) { a0 += __ldg(qrow + c); a1 += __ldg(qrow + c + 1); }
#pragma unroll
            for (int mt = 0; mt < 2; ++mt) {
                size_t r0 = (size_t)t * 64 + wm * 32 + mt * 16 + g;
                float2 pl = __half22float2(*(const __half2*)(g_pe + r0 * 256 + c));
                float2 ph = __half22float2(*(const __half2*)(g_pe + (r0 + 8) * 256 + c));
                __half2 lo = __floats2half2_rn(acc[mt][nt][0] + a0 + pl.x,
                                               acc[mt][nt][1] + a1 + pl.y);
                __half2 hi = __floats2half2_rn(acc[mt][nt][2] + a0 + ph.x,
                                               acc[mt][nt][3] + a1 + ph.y);
                *(__half2*)(dstArr + r0 * 256 + c)       = lo;
                *(__half2*)(dstArr + (r0 + 8) * 256 + c) = hi;
            }
        }
    }
}

// =======================================================================
// C: A1 = relu(h @ g1 + g1b) -> g_bufA. g1 resident 128KB. grid 152.
// =======================================================================
extern "C" __global__ void __launch_bounds__(512, 1)
pass_c(const float* __restrict__ g1b) {
    extern __shared__ char smem[];
    const unsigned int smb = (unsigned int)__cvta_generic_to_shared(smem);
    const int tid  = threadIdx.x;
    const int lane = tid & 31;
    const int wid  = tid >> 5;
    const int wm   = (wid >> 3) & 1, wnl = wid & 7;
    const int g    = lane >> 2, tig = lane & 3;
    const unsigned int DB = smb + 131072u;

    for (int i = tid; i < 8192; i += 512) {
        cp_async16(smb + (unsigned int)(i * 16), (const char*)g_g1B + i * 16);
    }
    const int t0 = blockIdx.x;
    stage_tile(DB, g_h, (size_t)t0 * 64, tid);
    CP_COMMIT();
    if (t0 + GRID1 < NTILES) {
        stage_tile(DB + 32768u, g_h, (size_t)(t0 + GRID1) * 64, tid);
        CP_COMMIT();
    }

    int it = 0;
    for (int t = t0; t < NTILES; t += GRID1, ++it) {
        if (t + GRID1 < NTILES) { CP_WAIT(1); } else { CP_WAIT(0); }
        __syncthreads();
        int t2 = t + 2 * GRID1;
        if (t2 < NTILES) {
            stage_tile(DB + (unsigned int)((it + 2) % 3) * 32768u, g_h, (size_t)t2 * 64, tid);
            CP_COMMIT();
        }
        float acc[2][4][4];
        ZERO_ACC(acc);
        compute_tile<16>(acc, DB + (unsigned int)(it % 3) * 32768u, 512u, smb, 8192u, lane, wm, wnl);
#pragma unroll
        for (int nt = 0; nt < 4; ++nt) {
            int c = wnl * 32 + nt * 8 + 2 * tig;
            float b0 = __ldg(g1b + c), b1 = __ldg(g1b + c + 1);
#pragma unroll
            for (int mt = 0; mt < 2; ++mt) {
                size_t r0 = (size_t)t * 64 + wm * 32 + mt * 16 + g;
                __half2 lo = __floats2half2_rn(fmaxf(acc[mt][nt][0] + b0, 0.f),
                                               fmaxf(acc[mt][nt][1] + b1, 0.f));
                __half2 hi = __floats2half2_rn(fmaxf(acc[mt][nt][2] + b0, 0.f),
                                               fmaxf(acc[mt][nt][3] + b1, 0.f));
                *(__half2*)(g_bufA + r0 * 256 + c)       = lo;
                *(__half2*)(g_bufA + (r0 + 8) * 256 + c) = hi;
            }
        }
    }
}

// =======================================================================
// D: logits = A1 @ g2 + g2b; softmax over 32 neighbors; res -> g_res16.
// =======================================================================
extern "C" __global__ void __launch_bounds__(512, 1)
pass_d(const float* __restrict__ g2b) {
    extern __shared__ char smem[];
    const unsigned int smb = (unsigned int)__cvta_generic_to_shared(smem);
    const int tid  = threadIdx.x;
    const int lane = tid & 31;
    const int wid  = tid >> 5;
    const int wm   = (wid >> 3) & 1, wnl = wid & 7;
    const int g    = lane >> 2, tig = lane & 3;
    const unsigned int DB = smb + 131072u;

    for (int i = tid; i < 8192; i += 512) {
        cp_async16(smb + (unsigned int)(i * 16), (const char*)g_g2B + i * 16);
    }
    const int t0 = blockIdx.x;
    stage_tile(DB, g_bufA, (size_t)t0 * 64, tid);
    CP_COMMIT();
    if (t0 + GRID1 < NTILES) {
        stage_tile(DB + 32768u, g_bufA, (size_t)(t0 + GRID1) * 64, tid);
        CP_COMMIT();
    }

    int it = 0;
    for (int t = t0; t < NTILES; t += GRID1, ++it) {
        if (t + GRID1 < NTILES) { CP_WAIT(1); } else { CP_WAIT(0); }
        __syncthreads();
        int t2 = t + 2 * GRID1;
        if (t2 < NTILES) {
            stage_tile(DB + (unsigned int)((it + 2) % 3) * 32768u, g_bufA, (size_t)t2 * 64, tid);
            CP_COMMIT();
        }
        float acc[2][4][4];
        ZERO_ACC(acc);
        compute_tile<16>(acc, DB + (unsigned int)(it % 3) * 32768u, 512u, smb, 8192u, lane, wm, wnl);
        const size_t rb = (size_t)t * 64 + wm * 32;
#pragma unroll
        for (int nt = 0; nt < 4; ++nt) {
            int c = wnl * 32 + nt * 8 + 2 * tig;
            float gb0 = __ldg(g2b + c), gb1 = __ldg(g2b + c + 1);
            float2 v00 = __half22float2(*(const __half2*)(g_vpe + (rb + g) * 256 + c));
            float2 v01 = __half22float2(*(const __half2*)(g_vpe + (rb + 8 + g) * 256 + c));
            float2 v10 = __half22float2(*(const __half2*)(g_vpe + (rb + 16 + g) * 256 + c));
            float2 v11 = __half22float2(*(const __half2*)(g_vpe + (rb + 24 + g) * 256 + c));
#pragma unroll
            for (int ci = 0; ci < 2; ++ci) {
                float gb = ci ? gb1 : gb0;
                float l0 = acc[0][nt][ci]     + gb;
                float l1 = acc[0][nt][ci + 2] + gb;
                float l2 = acc[1][nt][ci]     + gb;
                float l3 = acc[1][nt][ci + 2] + gb;
                float v0 = ci ? v00.y : v00.x;
                float v1 = ci ? v01.y : v01.x;
                float v2 = ci ? v10.y : v10.x;
                float v3 = ci ? v11.y : v11.x;
                float mx = fmaxf(fmaxf(l0, l1), fmaxf(l2, l3));
                mx = fmaxf(mx, __shfl_xor_sync(0xffffffffu, mx, 4));
                mx = fmaxf(mx, __shfl_xor_sync(0xffffffffu, mx, 8));
                mx = fmaxf(mx, __shfl_xor_sync(0xffffffffu, mx, 16));
                float e0 = __expf(l0 - mx), e1 = __expf(l1 - mx);
                float e2 = __expf(l2 - mx), e3 = __expf(l3 - mx);
                float ss = (e0 + e1) + (e2 + e3);
                float ws = (e0 * v0 + e1 * v1) + (e2 * v2 + e3 * v3);
                ss += __shfl_xor_sync(0xffffffffu, ss, 4);
                ws += __shfl_xor_sync(0xffffffffu, ws, 4);
                ss += __shfl_xor_sync(0xffffffffu, ss, 8);
                ws += __shfl_xor_sync(0xffffffffu, ws, 8);
                ss += __shfl_xor_sync(0xffffffffu, ss, 16);
                ws += __shfl_xor_sync(0xffffffffu, ws, 16);
                if (g == 0) {
                    g_res16[(size_t)(t * 2 + wm) * DIM + c + ci] = __float2half(ws / ss);
                }
            }
        }
    }
}

// =======================================================================
extern "C" void kernel_launch(void* const* d_in, const int* in_sizes, int n_in,
                              void* d_out, int out_size) {
    const float* xyz_q    = (const float*)d_in[0];
    const float* feats_q  = (const float*)d_in[1];
    const float* xyz_kv   = (const float*)d_in[2];
    const float* feats_kv = (const float*)d_in[3];
    const float* Wq       = (const float*)d_in[4];
    const float* Wk       = (const float*)d_in[5];
    const float* Wv       = (const float*)d_in[6];
    const float* d1w      = (const float*)d_in[7];
    const float* d1b      = (const float*)d_in[8];
    const float* d2w      = (const float*)d_in[9];
    const float* d2b      = (const float*)d_in[10];
    const float* g1w      = (const float*)d_in[11];
    const float* g1b      = (const float*)d_in[12];
    const float* g2w      = (const float*)d_in[13];
    const float* g2b      = (const float*)d_in[14];
    const float* ow       = (const float*)d_in[15];
    const float* obias    = (const float*)d_in[16];
    float* out = (float*)d_out;

    long long ofs = (long long)out_size - (long long)NPTS * DOUT;
    if (ofs < 0) ofs = 0;
    if (ofs > 0)
        copy_xyz_kernel<<<(int)((ofs + 255) / 256), 256>>>(xyz_q, out, (int)ofs);

    convert_all<<<1920, 256>>>(Wk, Wv, g1w, g2w, d2w, Wq, ow);
    convert_inputs<<<33792, 256>>>(feats_kv, feats_q);

    cudaFuncSetAttribute(pe_kernel,   cudaFuncAttributeMaxDynamicSharedMemorySize, 73728);
    cudaFuncSetAttribute(qproj_mma,   cudaFuncAttributeMaxDynamicSharedMemorySize, 163840);
    cudaFuncSetAttribute(outproj_mma, cudaFuncAttributeMaxDynamicSharedMemorySize, 163840);
    cudaFuncSetAttribute(pass_ab, cudaFuncAttributeMaxDynamicSharedMemorySize, 229376);
    cudaFuncSetAttribute(pass_c,  cudaFuncAttributeMaxDynamicSharedMemorySize, 229376);
    cudaFuncSetAttribute(pass_d,  cudaFuncAttributeMaxDynamicSharedMemorySize, 229376);

    qproj_mma<<<NQTILES, 512, 163840>>>();
    pe_kernel<<<2 * GRID1, 256, 73728>>>(xyz_q, xyz_kv, d1w, d1b);
    pass_ab<<<2 * GRID1, 512, 229376>>>(d2b);
    pass_c<<<GRID1, 512, 229376>>>(g1b);
    pass_d<<<GRID1, 512, 229376>>>(g2b);
    outproj_mma<<<2 * NQTILES, 512, 163840>>>(obias, out, ofs);
}